// round 2
// baseline (speedup 1.0000x reference)
#include <cuda_runtime.h>

// ---------------------------------------------------------------------------
// DigitConvolutionalModel: conv3x3(valid) -> FC(676->512)+relu -> FC(512->512)
// +relu -> FC(512->10). B = 32768. All fp32.
//
// Round 2: fix output-stage coverage bug (320 outputs/tile vs 256 threads).
//   Kernel 1: conv -> g_h0 scratch [B,676]
//   Kernel 2: per-32-row fused fc1+fc2+out, smem-tiled GEMMs.
// ---------------------------------------------------------------------------

#define BROWS   32768
#define CONVK   676      // 26*26
#define NHID    512
#define NOUT    10
#define MT      32       // rows per CTA in fused kernel
#define KT      16       // k-tile for weight staging
#define NTHR    256

// Scratch for conv output (static device global: allowed; no cudaMalloc).
__device__ float g_h0[(size_t)BROWS * CONVK];

// ---------------------------------------------------------------------------
// Conv kernel: h0[b, i*26+j] = sum_{di,dj} x[b,(i+di)*28 + (j+dj)] * w[di,dj]
// ---------------------------------------------------------------------------
__global__ void conv3x3_kernel(const float* __restrict__ x,
                               const float* __restrict__ w,
                               float* __restrict__ h0) {
    __shared__ float sw[9];
    int tid = threadIdx.x;
    if (tid < 9) sw[tid] = w[tid];
    __syncthreads();

    int idx = blockIdx.x * blockDim.x + tid;
    if (idx >= BROWS * CONVK) return;
    int b = idx / CONVK;
    int p = idx - b * CONVK;
    int i = p / 26;
    int j = p - i * 26;
    const float* xb = x + (size_t)b * 784 + i * 28 + j;
    float s = 0.0f;
#pragma unroll
    for (int di = 0; di < 3; di++) {
#pragma unroll
        for (int dj = 0; dj < 3; dj++) {
            s = fmaf(xb[di * 28 + dj], sw[di * 3 + dj], s);
        }
    }
    h0[idx] = s;
}

// ---------------------------------------------------------------------------
// Fused FC layer: sOut[m][512] = relu( sA[m][K] @ gw[512][K]^T + gb )
// sOut may alias sA (written only after a full __syncthreads()).
// Thread (tx = tid&31, ty = tid>>5) computes rows ty*4..+3, cols tx + j*32.
// ---------------------------------------------------------------------------
__device__ __forceinline__ void fc_layer(const float* __restrict__ sA,
                                         float* __restrict__ sW,
                                         const float* __restrict__ gw,
                                         const float* __restrict__ gb,
                                         float* __restrict__ sOut,
                                         int K, int tid) {
    const int tx = tid & 31;
    const int ty = tid >> 5;

    float C[4][16];
#pragma unroll
    for (int j = 0; j < 16; j++) {
        float bj = gb[tx + j * 32];
#pragma unroll
        for (int r = 0; r < 4; r++) C[r][j] = bj;
    }

    for (int k0 = 0; k0 < K; k0 += KT) {
        int kt = K - k0;
        if (kt > KT) kt = KT;

        __syncthreads();  // prior tile's reads of sW complete
        // Stage weight tile: sW[q][n] = gw[n][k0+q]; each thread owns 2 n-rows.
        for (int n = tid; n < NHID; n += NTHR) {
            const float* gwr = gw + (size_t)n * K + k0;
            for (int q = 0; q < kt; q += 4) {
                float4 v = *(const float4*)(gwr + q);
                sW[(q + 0) * NHID + n] = v.x;
                sW[(q + 1) * NHID + n] = v.y;
                sW[(q + 2) * NHID + n] = v.z;
                sW[(q + 3) * NHID + n] = v.w;
            }
        }
        __syncthreads();

        for (int q = 0; q < kt; q += 4) {
            float4 a[4];
#pragma unroll
            for (int r = 0; r < 4; r++)
                a[r] = *(const float4*)(sA + (ty * 4 + r) * K + k0 + q);
            const float* wq = sW + q * NHID + tx;
#pragma unroll
            for (int s = 0; s < 4; s++) {
                float av[4];
                av[0] = ((const float*)&a[0])[s];
                av[1] = ((const float*)&a[1])[s];
                av[2] = ((const float*)&a[2])[s];
                av[3] = ((const float*)&a[3])[s];
                const float* ws = wq + s * NHID;
#pragma unroll
                for (int j = 0; j < 16; j++) {
                    float bv = ws[j * 32];
#pragma unroll
                    for (int r = 0; r < 4; r++)
                        C[r][j] = fmaf(av[r], bv, C[r][j]);
                }
            }
        }
    }

    __syncthreads();  // all reads of sA done before (possibly aliased) stores
#pragma unroll
    for (int j = 0; j < 16; j++) {
#pragma unroll
        for (int r = 0; r < 4; r++) {
            float v = C[r][j];
            v = v > 0.0f ? v : 0.0f;
            sOut[(ty * 4 + r) * NHID + tx + j * 32] = v;
        }
    }
}

// ---------------------------------------------------------------------------
// Fused fc1 + fc2 + out for a 32-row tile.
// Smem: sA = 32*676 floats (reused as [32][512] for h1/h2), sW = 16*512 floats
// (reused for out_w staging). Total 119,360 B.
// ---------------------------------------------------------------------------
#define SA_FLOATS (MT * CONVK)         // 21632
#define SW_FLOATS (KT * NHID)          // 8192
#define SMEM_BYTES ((SA_FLOATS + SW_FLOATS + 16) * 4)

__global__ void __launch_bounds__(NTHR, 1)
mlp_fused_kernel(const float* __restrict__ fc1_w,
                 const float* __restrict__ fc1_b,
                 const float* __restrict__ fc2_w,
                 const float* __restrict__ fc2_b,
                 const float* __restrict__ out_w,
                 const float* __restrict__ out_b,
                 float* __restrict__ out) {
    extern __shared__ float smem[];
    float* sA = smem;                  // activations
    float* sW = smem + SA_FLOATS;      // weight staging

    const int tid = threadIdx.x;
    const int row0 = blockIdx.x * MT;

    // Load h0 tile [MT][676] coalesced (float4; 676 % 4 == 0).
    {
        const float4* src = (const float4*)(g_h0 + (size_t)row0 * CONVK);
        float4* dst = (float4*)sA;
#pragma unroll 4
        for (int i = tid; i < MT * CONVK / 4; i += NTHR) dst[i] = src[i];
    }
    // fc_layer's first __syncthreads() orders this load before compute.

    fc_layer(sA, sW, fc1_w, fc1_b, sA, CONVK, tid);  // h1 over sA, stride 512
    fc_layer(sA, sW, fc2_w, fc2_b, sA, NHID, tid);   // h2 over sA, stride 512

    __syncthreads();  // h2 stores visible; sW free

    // Stage out_w [10][512] + out_b into sW region (5130 <= 8192 floats).
    for (int i = tid; i < NOUT * NHID; i += NTHR) sW[i] = out_w[i];
    if (tid < NOUT) sW[NOUT * NHID + tid] = out_b[tid];
    __syncthreads();

    // 320 outputs per tile; strided so ALL are covered by 256 threads.
    for (int i = tid; i < MT * NOUT; i += NTHR) {
        int m = i / NOUT;
        int n = i - m * NOUT;
        const float* h = sA + m * NHID;
        const float* w = sW + n * NHID;
        float s = sW[NOUT * NHID + n];
#pragma unroll 8
        for (int k = 0; k < NHID; k += 4) {
            float4 hv = *(const float4*)(h + k);
            float4 wv = *(const float4*)(w + k);
            s = fmaf(hv.x, wv.x, s);
            s = fmaf(hv.y, wv.y, s);
            s = fmaf(hv.z, wv.z, s);
            s = fmaf(hv.w, wv.w, s);
        }
        out[(size_t)row0 * NOUT + i] = s;  // coalesced within the tile
    }
}

// ---------------------------------------------------------------------------
// Launch
// ---------------------------------------------------------------------------
extern "C" void kernel_launch(void* const* d_in, const int* in_sizes, int n_in,
                              void* d_out, int out_size) {
    const float* x      = (const float*)d_in[0];
    const float* conv_w = (const float*)d_in[1];
    const float* fc1_w  = (const float*)d_in[2];
    const float* fc1_b  = (const float*)d_in[3];
    const float* fc2_w  = (const float*)d_in[4];
    const float* fc2_b  = (const float*)d_in[5];
    const float* out_w  = (const float*)d_in[6];
    const float* out_b  = (const float*)d_in[7];
    float* out = (float*)d_out;

    float* h0;
    cudaGetSymbolAddress((void**)&h0, g_h0);

    // Conv
    {
        int total = BROWS * CONVK;
        int blocks = (total + NTHR - 1) / NTHR;
        conv3x3_kernel<<<blocks, NTHR>>>(x, conv_w, h0);
    }

    // Fused MLP
    {
        cudaFuncSetAttribute(mlp_fused_kernel,
                             cudaFuncAttributeMaxDynamicSharedMemorySize,
                             SMEM_BYTES);
        int blocks = BROWS / MT;  // 1024
        mlp_fused_kernel<<<blocks, NTHR, SMEM_BYTES>>>(
            fc1_w, fc1_b, fc2_w, fc2_b, out_w, out_b, out);
    }
}

// round 9
// speedup vs baseline: 5.8098x; 5.8098x over previous
#include <cuda_runtime.h>
#include <cuda_bf16.h>
#include <cstdint>

// ---------------------------------------------------------------------------
// DigitConvolutionalModel via warp-level mma.sync (bf16, split hi/lo, fp32
// accum). No tcgen05 / TMEM / mbarrier / clusters — plain PTX, graph-safe.
//   conv_split: conv3x3 -> h0 hi/lo bf16 [B][704]
//   wprep:      split fc1_w (pad 676->704) and fc2_w into hi/lo bf16
//   gemm<0>:    h1 = relu(h0 @ w1^T + b1) -> split bf16 h1 hi/lo
//   gemm<1>:    h2 = relu(h1 @ w2^T + b2) -> fp32 h2
//   out_kernel: logits = h2 @ out_w^T + out_b
// 3 MMA passes per k-step: Ah*Bh + Ah*Bl + Al*Bh (Al*Bl ~2^-16, dropped).
// ---------------------------------------------------------------------------

#define BROWS  32768
#define K1RAW  676
#define K1PAD  704          // 22 * 32
#define K2     512
#define NHID   512
#define NOUT   10
#define CTHR   256

// GEMM tiling
#define BM 128
#define BN 128
#define BK 32
#define GTHR 256            // 8 warps: 4 (m) x 2 (n); warp tile 32 x 64
#define KS 20               // smem row stride in u32 (= 40 bf16), conflict-free

// ---- scratch (static device globals; no allocation APIs) -------------------
__device__ __align__(16) __nv_bfloat16 g_h0h[(size_t)BROWS * K1PAD];
__device__ __align__(16) __nv_bfloat16 g_h0l[(size_t)BROWS * K1PAD];
__device__ __align__(16) __nv_bfloat16 g_w1h[(size_t)NHID * K1PAD];
__device__ __align__(16) __nv_bfloat16 g_w1l[(size_t)NHID * K1PAD];
__device__ __align__(16) __nv_bfloat16 g_w2h[(size_t)NHID * K2];
__device__ __align__(16) __nv_bfloat16 g_w2l[(size_t)NHID * K2];
__device__ __align__(16) __nv_bfloat16 g_h1h[(size_t)BROWS * K2];
__device__ __align__(16) __nv_bfloat16 g_h1l[(size_t)BROWS * K2];
__device__ __align__(16) float         g_h2[(size_t)BROWS * NHID];

// ---- helpers ---------------------------------------------------------------
__device__ __forceinline__ void split_bf16(float x, __nv_bfloat16& h,
                                           __nv_bfloat16& l) {
    h = __float2bfloat16(x);
    l = __float2bfloat16(x - __bfloat162float(h));
}
__device__ __forceinline__ uint32_t pack_split_hi(float a, float b,
                                                  uint32_t& lo_pack) {
    __nv_bfloat16 ha, la, hb, lb;
    split_bf16(a, ha, la);
    split_bf16(b, hb, lb);
    lo_pack = (uint32_t)__bfloat16_as_ushort(la) |
              ((uint32_t)__bfloat16_as_ushort(lb) << 16);
    return (uint32_t)__bfloat16_as_ushort(ha) |
           ((uint32_t)__bfloat16_as_ushort(hb) << 16);
}

// m16n8k16 row.col bf16 MMA, fp32 accum (plain PTX, sm_80+)
__device__ __forceinline__ void mma16816(float* c, const uint32_t* a,
                                         const uint32_t* b) {
    asm volatile(
        "mma.sync.aligned.m16n8k16.row.col.f32.bf16.bf16.f32 "
        "{%0,%1,%2,%3}, {%4,%5,%6,%7}, {%8,%9}, {%0,%1,%2,%3};"
        : "+f"(c[0]), "+f"(c[1]), "+f"(c[2]), "+f"(c[3])
        : "r"(a[0]), "r"(a[1]), "r"(a[2]), "r"(a[3]), "r"(b[0]), "r"(b[1]));
}

// ---------------------------------------------------------------------------
// conv + split: g_h0{h,l}[b][k], k in [0,704), zero-padded past 676.
// ---------------------------------------------------------------------------
__global__ void conv_split_kernel(const float* __restrict__ x,
                                  const float* __restrict__ w) {
    __shared__ float sw[9];
    int tid = threadIdx.x;
    if (tid < 9) sw[tid] = w[tid];
    __syncthreads();

    size_t idx = (size_t)blockIdx.x * blockDim.x + tid;
    if (idx >= (size_t)BROWS * K1PAD) return;
    int b = (int)(idx / K1PAD);
    int p = (int)(idx - (size_t)b * K1PAD);
    float s = 0.0f;
    if (p < K1RAW) {
        int i = p / 26, j = p - i * 26;
        const float* xb = x + (size_t)b * 784 + i * 28 + j;
#pragma unroll
        for (int di = 0; di < 3; di++)
#pragma unroll
            for (int dj = 0; dj < 3; dj++)
                s = fmaf(xb[di * 28 + dj], sw[di * 3 + dj], s);
    }
    __nv_bfloat16 h, l;
    split_bf16(s, h, l);
    g_h0h[idx] = h;
    g_h0l[idx] = l;
}

// ---------------------------------------------------------------------------
// weight split prep
// ---------------------------------------------------------------------------
__global__ void wprep_kernel(const float* __restrict__ w1,
                             const float* __restrict__ w2) {
    int idx = blockIdx.x * blockDim.x + threadIdx.x;
    int n1 = NHID * K1PAD;
    if (idx < n1) {
        int n = idx / K1PAD, k = idx - n * K1PAD;
        float v = (k < K1RAW) ? w1[n * K1RAW + k] : 0.0f;
        __nv_bfloat16 h, l;
        split_bf16(v, h, l);
        g_w1h[idx] = h;
        g_w1l[idx] = l;
    } else {
        int j = idx - n1;
        if (j < NHID * K2) {
            float v = w2[j];
            __nv_bfloat16 h, l;
            split_bf16(v, h, l);
            g_w2h[j] = h;
            g_w2l[j] = l;
        }
    }
}

// ---------------------------------------------------------------------------
// Tiled GEMM: C[BM x BN] = A[BM x K] @ W[BN x K]^T, split-bf16 3-pass.
// MODE 0: out = relu(C + bias) split -> (outH, outL) bf16, width 512
// MODE 1: out = relu(C + bias) -> outF fp32, width 512
// grid = (BN tiles = 4, BM tiles = 256), 256 threads.
// ---------------------------------------------------------------------------
template <int MODE>
__global__ void __launch_bounds__(GTHR, 2)
gemm_kernel(const __nv_bfloat16* __restrict__ Ah,
            const __nv_bfloat16* __restrict__ Al,
            const __nv_bfloat16* __restrict__ Wh,
            const __nv_bfloat16* __restrict__ Wl,
            const float* __restrict__ bias, int K,
            __nv_bfloat16* __restrict__ outH,
            __nv_bfloat16* __restrict__ outL,
            float* __restrict__ outF) {
    __shared__ uint32_t sAh[BM * KS], sAl[BM * KS];
    __shared__ uint32_t sBh[BN * KS], sBl[BN * KS];
    __shared__ float sBias[BN];

    const int tid = threadIdx.x;
    const int lane = tid & 31;
    const int warp = tid >> 5;
    const int wm = warp & 3;             // 0..3
    const int wn = warp >> 2;            // 0..1
    const size_t rowA0 = (size_t)blockIdx.y * BM;
    const int ncol0 = blockIdx.x * BN;

    if (tid < BN) sBias[tid] = bias[ncol0 + tid];

    float c[2][8][4];
#pragma unroll
    for (int mt = 0; mt < 2; mt++)
#pragma unroll
        for (int nt = 0; nt < 8; nt++)
#pragma unroll
            for (int i = 0; i < 4; i++) c[mt][nt][i] = 0.0f;

    const int lq = lane >> 2;            // 0..7
    const int lr = lane & 3;             // 0..3

    const int kcn = K / BK;
    for (int kc = 0; kc < kcn; kc++) {
        __syncthreads();
        // stage A and B chunks: [128 rows][32 bf16] each, hi+lo
        for (int i = tid; i < 512; i += GTHR) {
            int row = i >> 2, quad = i & 3;
            size_t ga = (rowA0 + row) * (size_t)K + kc * BK + quad * 8;
            size_t gb = (size_t)(ncol0 + row) * K + kc * BK + quad * 8;
            *(uint4*)&sAh[row * KS + quad * 4] = *(const uint4*)(Ah + ga);
            *(uint4*)&sAl[row * KS + quad * 4] = *(const uint4*)(Al + ga);
            *(uint4*)&sBh[row * KS + quad * 4] = *(const uint4*)(Wh + gb);
            *(uint4*)&sBl[row * KS + quad * 4] = *(const uint4*)(Wl + gb);
        }
        __syncthreads();

#pragma unroll
        for (int ks = 0; ks < 2; ks++) {
            const int cidx = ks * 8 + lr;
            uint32_t afh[2][4], afl[2][4];
#pragma unroll
            for (int mt = 0; mt < 2; mt++) {
                int r = wm * 32 + mt * 16 + lq;
                afh[mt][0] = sAh[r * KS + cidx];
                afh[mt][1] = sAh[(r + 8) * KS + cidx];
                afh[mt][2] = sAh[r * KS + cidx + 4];
                afh[mt][3] = sAh[(r + 8) * KS + cidx + 4];
                afl[mt][0] = sAl[r * KS + cidx];
                afl[mt][1] = sAl[(r + 8) * KS + cidx];
                afl[mt][2] = sAl[r * KS + cidx + 4];
                afl[mt][3] = sAl[(r + 8) * KS + cidx + 4];
            }
#pragma unroll
            for (int nt = 0; nt < 8; nt++) {
                int n = wn * 64 + nt * 8 + lq;
                uint32_t bfh[2], bfl[2];
                bfh[0] = sBh[n * KS + cidx];
                bfh[1] = sBh[n * KS + cidx + 4];
                bfl[0] = sBl[n * KS + cidx];
                bfl[1] = sBl[n * KS + cidx + 4];
#pragma unroll
                for (int mt = 0; mt < 2; mt++) {
                    mma16816(c[mt][nt], afh[mt], bfh);
                    mma16816(c[mt][nt], afh[mt], bfl);
                    mma16816(c[mt][nt], afl[mt], bfh);
                }
            }
        }
    }

    // epilogue
#pragma unroll
    for (int mt = 0; mt < 2; mt++) {
        size_t r0 = rowA0 + wm * 32 + mt * 16 + lq;
        size_t r1 = r0 + 8;
#pragma unroll
        for (int nt = 0; nt < 8; nt++) {
            int nl = wn * 64 + nt * 8 + lr * 2;
            int ng = ncol0 + nl;
            float b0 = sBias[nl], b1 = sBias[nl + 1];
            float v00 = fmaxf(c[mt][nt][0] + b0, 0.0f);
            float v01 = fmaxf(c[mt][nt][1] + b1, 0.0f);
            float v10 = fmaxf(c[mt][nt][2] + b0, 0.0f);
            float v11 = fmaxf(c[mt][nt][3] + b1, 0.0f);
            if (MODE == 0) {
                uint32_t lo0, lo1;
                uint32_t hi0 = pack_split_hi(v00, v01, lo0);
                uint32_t hi1 = pack_split_hi(v10, v11, lo1);
                *(uint32_t*)(outH + r0 * NHID + ng) = hi0;
                *(uint32_t*)(outL + r0 * NHID + ng) = lo0;
                *(uint32_t*)(outH + r1 * NHID + ng) = hi1;
                *(uint32_t*)(outL + r1 * NHID + ng) = lo1;
            } else {
                *(float2*)(outF + r0 * NHID + ng) = make_float2(v00, v01);
                *(float2*)(outF + r1 * NHID + ng) = make_float2(v10, v11);
            }
        }
    }
}

// ---------------------------------------------------------------------------
// out layer: logits[b][o] = h2[b] . out_w[o] + out_b[o].  Warp per row.
// ---------------------------------------------------------------------------
__global__ void __launch_bounds__(128)
out_kernel(const float* __restrict__ h2,
           const float* __restrict__ out_w,
           const float* __restrict__ out_b,
           float* __restrict__ out) {
    __shared__ float sw[NOUT * NHID];
    __shared__ float sb[NOUT];
    int tid = threadIdx.x;
    for (int i = tid; i < NOUT * NHID; i += 128) sw[i] = out_w[i];
    if (tid < NOUT) sb[tid] = out_b[tid];
    __syncthreads();

    int lane = tid & 31, warp = tid >> 5;
    size_t row = (size_t)blockIdx.x * 4 + warp;
    const float* hr = h2 + row * NHID;

    float part[NOUT];
#pragma unroll
    for (int o = 0; o < NOUT; o++) part[o] = 0.0f;

    for (int k = lane; k < NHID; k += 32) {
        float v = hr[k];
#pragma unroll
        for (int o = 0; o < NOUT; o++)
            part[o] = fmaf(v, sw[o * NHID + k], part[o]);
    }
#pragma unroll
    for (int off = 16; off > 0; off >>= 1)
#pragma unroll
        for (int o = 0; o < NOUT; o++)
            part[o] += __shfl_xor_sync(0xFFFFFFFF, part[o], off);

    if (lane < NOUT) out[row * NOUT + lane] = part[lane] + sb[lane];
}

// ---------------------------------------------------------------------------
// Launch
// ---------------------------------------------------------------------------
extern "C" void kernel_launch(void* const* d_in, const int* in_sizes, int n_in,
                              void* d_out, int out_size) {
    const float* x      = (const float*)d_in[0];
    const float* conv_w = (const float*)d_in[1];
    const float* fc1_w  = (const float*)d_in[2];
    const float* fc1_b  = (const float*)d_in[3];
    const float* fc2_w  = (const float*)d_in[4];
    const float* fc2_b  = (const float*)d_in[5];
    const float* out_w  = (const float*)d_in[6];
    const float* out_b  = (const float*)d_in[7];
    float* out = (float*)d_out;

    __nv_bfloat16 *h0h, *h0l, *w1h, *w1l, *w2h, *w2l, *h1h, *h1l;
    float* h2;
    cudaGetSymbolAddress((void**)&h0h, g_h0h);
    cudaGetSymbolAddress((void**)&h0l, g_h0l);
    cudaGetSymbolAddress((void**)&w1h, g_w1h);
    cudaGetSymbolAddress((void**)&w1l, g_w1l);
    cudaGetSymbolAddress((void**)&w2h, g_w2h);
    cudaGetSymbolAddress((void**)&w2l, g_w2l);
    cudaGetSymbolAddress((void**)&h1h, g_h1h);
    cudaGetSymbolAddress((void**)&h1l, g_h1l);
    cudaGetSymbolAddress((void**)&h2, g_h2);

    // weight split
    {
        int total = NHID * K1PAD + NHID * K2;
        wprep_kernel<<<(total + CTHR - 1) / CTHR, CTHR>>>(fc1_w, fc2_w);
    }
    // conv + split
    {
        size_t total = (size_t)BROWS * K1PAD;
        conv_split_kernel<<<(int)((total + CTHR - 1) / CTHR), CTHR>>>(x, conv_w);
    }
    // fc1: h1 = relu(h0 @ w1^T + b1), split bf16
    {
        dim3 grid(NHID / BN, BROWS / BM);
        gemm_kernel<0><<<grid, GTHR>>>(h0h, h0l, w1h, w1l, fc1_b, K1PAD,
                                       h1h, h1l, nullptr);
    }
    // fc2: h2 = relu(h1 @ w2^T + b2), fp32
    {
        dim3 grid(NHID / BN, BROWS / BM);
        gemm_kernel<1><<<grid, GTHR>>>(h1h, h1l, w2h, w2l, fc2_b, K2,
                                       nullptr, nullptr, h2);
    }
    // out layer
    out_kernel<<<BROWS / 4, 128>>>(h2, out_w, out_b, out);
}

// round 10
// speedup vs baseline: 6.7544x; 1.1626x over previous
#include <cuda_runtime.h>
#include <cuda_bf16.h>
#include <cstdint>

// ---------------------------------------------------------------------------
// DigitConvolutionalModel via warp-level mma.sync (bf16 split hi/lo, fp32
// accum), R10: ldmatrix.x4 fragment loads + cp.async double-buffered staging.
//   conv_split: conv3x3 -> h0 hi/lo bf16 [B][704]
//   wprep:      split fc1_w (pad 676->704) and fc2_w into hi/lo bf16
//   gemm<0>:    h1 = relu(h0 @ w1^T + b1) -> split bf16 h1 hi/lo
//   gemm<1>:    h2 = relu(h1 @ w2^T + b2) -> fp32 h2
//   out_kernel: logits = h2 @ out_w^T + out_b
// 3 MMA passes per k-step: Ah*Bh + Ah*Bl + Al*Bh (Al*Bl ~2^-16, dropped).
// ---------------------------------------------------------------------------

#define BROWS  32768
#define K1RAW  676
#define K1PAD  704          // 22 * 32
#define K2     512
#define NHID   512
#define NOUT   10
#define CTHR   256

// GEMM tiling
#define BM 128
#define BN 128
#define BK 32
#define GTHR 256            // 8 warps: 4 (m) x 2 (n); warp tile 32 x 64
#define KS 20               // smem row stride in u32 (80 B): 16B-aligned rows,
                            // 5x16B stride -> conflict-free ldmatrix

// dynamic smem layout (u32 units)
#define ST_A_H   0
#define ST_A_L   2560
#define ST_B_H   5120
#define ST_B_L   7680
#define ST_SIZE  10240              // one stage = 40960 B
#define ST_BIAS  (2 * ST_SIZE)      // float[128] after both stages
#define DSMEM_BYTES (2 * ST_SIZE * 4 + 512)

// ---- scratch (static device globals; no allocation APIs) -------------------
__device__ __align__(16) __nv_bfloat16 g_h0h[(size_t)BROWS * K1PAD];
__device__ __align__(16) __nv_bfloat16 g_h0l[(size_t)BROWS * K1PAD];
__device__ __align__(16) __nv_bfloat16 g_w1h[(size_t)NHID * K1PAD];
__device__ __align__(16) __nv_bfloat16 g_w1l[(size_t)NHID * K1PAD];
__device__ __align__(16) __nv_bfloat16 g_w2h[(size_t)NHID * K2];
__device__ __align__(16) __nv_bfloat16 g_w2l[(size_t)NHID * K2];
__device__ __align__(16) __nv_bfloat16 g_h1h[(size_t)BROWS * K2];
__device__ __align__(16) __nv_bfloat16 g_h1l[(size_t)BROWS * K2];
__device__ __align__(16) float         g_h2[(size_t)BROWS * NHID];

// ---- helpers ---------------------------------------------------------------
__device__ __forceinline__ void split_bf16(float x, __nv_bfloat16& h,
                                           __nv_bfloat16& l) {
    h = __float2bfloat16(x);
    l = __float2bfloat16(x - __bfloat162float(h));
}
__device__ __forceinline__ uint32_t pack_split_hi(float a, float b,
                                                  uint32_t& lo_pack) {
    __nv_bfloat16 ha, la, hb, lb;
    split_bf16(a, ha, la);
    split_bf16(b, hb, lb);
    lo_pack = (uint32_t)__bfloat16_as_ushort(la) |
              ((uint32_t)__bfloat16_as_ushort(lb) << 16);
    return (uint32_t)__bfloat16_as_ushort(ha) |
           ((uint32_t)__bfloat16_as_ushort(hb) << 16);
}

__device__ __forceinline__ void mma16816(float* c, const uint32_t* a,
                                         const uint32_t* b) {
    asm volatile(
        "mma.sync.aligned.m16n8k16.row.col.f32.bf16.bf16.f32 "
        "{%0,%1,%2,%3}, {%4,%5,%6,%7}, {%8,%9}, {%0,%1,%2,%3};"
        : "+f"(c[0]), "+f"(c[1]), "+f"(c[2]), "+f"(c[3])
        : "r"(a[0]), "r"(a[1]), "r"(a[2]), "r"(a[3]), "r"(b[0]), "r"(b[1]));
}
#define LDSM4(r, addr) \
    asm volatile("ldmatrix.sync.aligned.m8n8.x4.shared.b16 {%0,%1,%2,%3}, [%4];" \
        : "=r"((r)[0]), "=r"((r)[1]), "=r"((r)[2]), "=r"((r)[3]) : "r"(addr))
__device__ __forceinline__ void cp16(uint32_t saddr, const void* gaddr) {
    asm volatile("cp.async.cg.shared.global [%0], [%1], 16;"
                 :: "r"(saddr), "l"(gaddr));
}
#define CP_COMMIT() asm volatile("cp.async.commit_group;" ::: "memory")
#define CP_WAIT(n)  asm volatile("cp.async.wait_group %0;" :: "n"(n) : "memory")

// ---------------------------------------------------------------------------
// conv + split: g_h0{h,l}[b][k], k in [0,704), zero-padded past 676.
// ---------------------------------------------------------------------------
__global__ void conv_split_kernel(const float* __restrict__ x,
                                  const float* __restrict__ w) {
    __shared__ float sw[9];
    int tid = threadIdx.x;
    if (tid < 9) sw[tid] = w[tid];
    __syncthreads();

    size_t idx = (size_t)blockIdx.x * blockDim.x + tid;
    if (idx >= (size_t)BROWS * K1PAD) return;
    int b = (int)(idx / K1PAD);
    int p = (int)(idx - (size_t)b * K1PAD);
    float s = 0.0f;
    if (p < K1RAW) {
        int i = p / 26, j = p - i * 26;
        const float* xb = x + (size_t)b * 784 + i * 28 + j;
#pragma unroll
        for (int di = 0; di < 3; di++)
#pragma unroll
            for (int dj = 0; dj < 3; dj++)
                s = fmaf(xb[di * 28 + dj], sw[di * 3 + dj], s);
    }
    __nv_bfloat16 h, l;
    split_bf16(s, h, l);
    g_h0h[idx] = h;
    g_h0l[idx] = l;
}

// ---------------------------------------------------------------------------
// weight split prep
// ---------------------------------------------------------------------------
__global__ void wprep_kernel(const float* __restrict__ w1,
                             const float* __restrict__ w2) {
    int idx = blockIdx.x * blockDim.x + threadIdx.x;
    int n1 = NHID * K1PAD;
    if (idx < n1) {
        int n = idx / K1PAD, k = idx - n * K1PAD;
        float v = (k < K1RAW) ? w1[n * K1RAW + k] : 0.0f;
        __nv_bfloat16 h, l;
        split_bf16(v, h, l);
        g_w1h[idx] = h;
        g_w1l[idx] = l;
    } else {
        int j = idx - n1;
        if (j < NHID * K2) {
            float v = w2[j];
            __nv_bfloat16 h, l;
            split_bf16(v, h, l);
            g_w2h[j] = h;
            g_w2l[j] = l;
        }
    }
}

// ---------------------------------------------------------------------------
// Tiled GEMM: C[BM x BN] = A[BM x K] @ W[BN x K]^T, split-bf16 3-pass,
// cp.async double-buffered, ldmatrix fragment loads.
// MODE 0: out = relu(C + bias) split -> (outH, outL) bf16, width 512
// MODE 1: out = relu(C + bias) -> outF fp32, width 512
// ---------------------------------------------------------------------------
template <int MODE>
__global__ void __launch_bounds__(GTHR, 2)
gemm_kernel(const __nv_bfloat16* __restrict__ Ah,
            const __nv_bfloat16* __restrict__ Al,
            const __nv_bfloat16* __restrict__ Wh,
            const __nv_bfloat16* __restrict__ Wl,
            const float* __restrict__ bias, int K,
            __nv_bfloat16* __restrict__ outH,
            __nv_bfloat16* __restrict__ outL,
            float* __restrict__ outF) {
    extern __shared__ uint32_t dsm[];
    float* sBias = (float*)(dsm + ST_BIAS);
    const uint32_t sbase =
        (uint32_t)__cvta_generic_to_shared(dsm);

    const int tid = threadIdx.x;
    const int lane = tid & 31;
    const int warp = tid >> 5;
    const int wm = warp & 3;
    const int wn = warp >> 2;
    const size_t rowA0 = (size_t)blockIdx.y * BM;
    const int ncol0 = blockIdx.x * BN;

    if (tid < BN) sBias[tid] = bias[ncol0 + tid];

    float c[2][8][4];
#pragma unroll
    for (int mt = 0; mt < 2; mt++)
#pragma unroll
        for (int nt = 0; nt < 8; nt++)
#pragma unroll
            for (int i = 0; i < 4; i++) c[mt][nt][i] = 0.0f;

    const int kcn = K / BK;

    // ---- staging (cp.async): one k-chunk into stage s ----
    auto stage = [&](int kc, int s) {
        uint32_t sb = sbase + (uint32_t)(s * ST_SIZE * 4);
#pragma unroll
        for (int it = 0; it < 2; it++) {
            int i = tid + it * GTHR;           // 0..511
            int row = i >> 2, quad = i & 3;
            uint32_t soff = (uint32_t)(row * 80 + quad * 16);
            size_t ga = (rowA0 + row) * (size_t)K + kc * BK + quad * 8;
            size_t gb = (size_t)(ncol0 + row) * K + kc * BK + quad * 8;
            cp16(sb + ST_A_H * 4 + soff, Ah + ga);
            cp16(sb + ST_A_L * 4 + soff, Al + ga);
            cp16(sb + ST_B_H * 4 + soff, Wh + gb);
            cp16(sb + ST_B_L * 4 + soff, Wl + gb);
        }
    };

    stage(0, 0);
    CP_COMMIT();

    for (int kc = 0; kc < kcn; kc++) {
        if (kc + 1 < kcn) {
            stage(kc + 1, (kc + 1) & 1);
            CP_COMMIT();
            CP_WAIT(1);
        } else {
            CP_WAIT(0);
        }
        __syncthreads();

        const uint32_t sb = sbase + (uint32_t)((kc & 1) * ST_SIZE * 4);
        const uint32_t aAh = sb + ST_A_H * 4;
        const uint32_t aAl = sb + ST_A_L * 4;
        const uint32_t aBh = sb + ST_B_H * 4;
        const uint32_t aBl = sb + ST_B_L * 4;

        const int g = lane >> 3, lr8 = lane & 7;

#pragma unroll
        for (int ks = 0; ks < 2; ks++) {
            // A fragments: matrices {r0-7/k0-7, r8-15/k0-7, r0-7/k8-15, r8-15/k8-15}
            uint32_t ah[2][4], al[2][4];
            {
                const int rsel = (g & 1) ? 8 : 0;
                const int bsel = (g & 2) ? 16 : 0;
#pragma unroll
                for (int mt = 0; mt < 2; mt++) {
                    int r = wm * 32 + mt * 16 + lr8 + rsel;
                    uint32_t off = (uint32_t)(r * 80 + ks * 32 + bsel);
                    LDSM4(ah[mt], aAh + off);
                    LDSM4(al[mt], aAl + off);
                }
            }
            // B fragments: x4 covers 16 n-rows -> two n-blocks of 8
            {
                const int rsel = (g & 2) ? 8 : 0;
                const int bsel = (g & 1) ? 16 : 0;
#pragma unroll
                for (int np = 0; np < 4; np++) {
                    int nr = wn * 64 + np * 16 + lr8 + rsel;
                    uint32_t off = (uint32_t)(nr * 80 + ks * 32 + bsel);
                    uint32_t bh[4], bl[4];
                    LDSM4(bh, aBh + off);
                    LDSM4(bl, aBl + off);
#pragma unroll
                    for (int hf = 0; hf < 2; hf++) {
                        int nt = np * 2 + hf;
#pragma unroll
                        for (int mt = 0; mt < 2; mt++) {
                            mma16816(c[mt][nt], ah[mt], bh + 2 * hf);
                            mma16816(c[mt][nt], ah[mt], bl + 2 * hf);
                            mma16816(c[mt][nt], al[mt], bh + 2 * hf);
                        }
                    }
                }
            }
        }
        __syncthreads();   // all reads done before stage kc+2 overwrites
    }

    // epilogue (c-frag layout: c0,c1 -> row lq, cols 2lr,2lr+1; c2,c3 -> row lq+8)
    const int lq = lane >> 2;
    const int lr = lane & 3;
#pragma unroll
    for (int mt = 0; mt < 2; mt++) {
        size_t r0 = rowA0 + wm * 32 + mt * 16 + lq;
        size_t r1 = r0 + 8;
#pragma unroll
        for (int nt = 0; nt < 8; nt++) {
            int nl = wn * 64 + nt * 8 + lr * 2;
            int ng = ncol0 + nl;
            float b0 = sBias[nl], b1 = sBias[nl + 1];
            float v00 = fmaxf(c[mt][nt][0] + b0, 0.0f);
            float v01 = fmaxf(c[mt][nt][1] + b1, 0.0f);
            float v10 = fmaxf(c[mt][nt][2] + b0, 0.0f);
            float v11 = fmaxf(c[mt][nt][3] + b1, 0.0f);
            if (MODE == 0) {
                uint32_t lo0, lo1;
                uint32_t hi0 = pack_split_hi(v00, v01, lo0);
                uint32_t hi1 = pack_split_hi(v10, v11, lo1);
                *(uint32_t*)(outH + r0 * NHID + ng) = hi0;
                *(uint32_t*)(outL + r0 * NHID + ng) = lo0;
                *(uint32_t*)(outH + r1 * NHID + ng) = hi1;
                *(uint32_t*)(outL + r1 * NHID + ng) = lo1;
            } else {
                *(float2*)(outF + r0 * NHID + ng) = make_float2(v00, v01);
                *(float2*)(outF + r1 * NHID + ng) = make_float2(v10, v11);
            }
        }
    }
}

// ---------------------------------------------------------------------------
// out layer: logits[b][o] = h2[b] . out_w[o] + out_b[o].  Warp per row.
// ---------------------------------------------------------------------------
__global__ void __launch_bounds__(128)
out_kernel(const float* __restrict__ h2,
           const float* __restrict__ out_w,
           const float* __restrict__ out_b,
           float* __restrict__ out) {
    __shared__ float sw[NOUT * NHID];
    __shared__ float sb[NOUT];
    int tid = threadIdx.x;
    for (int i = tid; i < NOUT * NHID; i += 128) sw[i] = out_w[i];
    if (tid < NOUT) sb[tid] = out_b[tid];
    __syncthreads();

    int lane = tid & 31, warp = tid >> 5;
    size_t row = (size_t)blockIdx.x * 4 + warp;
    const float* hr = h2 + row * NHID;

    float part[NOUT];
#pragma unroll
    for (int o = 0; o < NOUT; o++) part[o] = 0.0f;

    for (int k = lane; k < NHID; k += 32) {
        float v = hr[k];
#pragma unroll
        for (int o = 0; o < NOUT; o++)
            part[o] = fmaf(v, sw[o * NHID + k], part[o]);
    }
#pragma unroll
    for (int off = 16; off > 0; off >>= 1)
#pragma unroll
        for (int o = 0; o < NOUT; o++)
            part[o] += __shfl_xor_sync(0xFFFFFFFF, part[o], off);

    if (lane < NOUT) out[row * NOUT + lane] = part[lane] + sb[lane];
}

// ---------------------------------------------------------------------------
// Launch
// ---------------------------------------------------------------------------
extern "C" void kernel_launch(void* const* d_in, const int* in_sizes, int n_in,
                              void* d_out, int out_size) {
    const float* x      = (const float*)d_in[0];
    const float* conv_w = (const float*)d_in[1];
    const float* fc1_w  = (const float*)d_in[2];
    const float* fc1_b  = (const float*)d_in[3];
    const float* fc2_w  = (const float*)d_in[4];
    const float* fc2_b  = (const float*)d_in[5];
    const float* out_w  = (const float*)d_in[6];
    const float* out_b  = (const float*)d_in[7];
    float* out = (float*)d_out;

    __nv_bfloat16 *h0h, *h0l, *w1h, *w1l, *w2h, *w2l, *h1h, *h1l;
    float* h2;
    cudaGetSymbolAddress((void**)&h0h, g_h0h);
    cudaGetSymbolAddress((void**)&h0l, g_h0l);
    cudaGetSymbolAddress((void**)&w1h, g_w1h);
    cudaGetSymbolAddress((void**)&w1l, g_w1l);
    cudaGetSymbolAddress((void**)&w2h, g_w2h);
    cudaGetSymbolAddress((void**)&w2l, g_w2l);
    cudaGetSymbolAddress((void**)&h1h, g_h1h);
    cudaGetSymbolAddress((void**)&h1l, g_h1l);
    cudaGetSymbolAddress((void**)&h2, g_h2);

    // weight split
    {
        int total = NHID * K1PAD + NHID * K2;
        wprep_kernel<<<(total + CTHR - 1) / CTHR, CTHR>>>(fc1_w, fc2_w);
    }
    // conv + split
    {
        size_t total = (size_t)BROWS * K1PAD;
        conv_split_kernel<<<(int)((total + CTHR - 1) / CTHR), CTHR>>>(x, conv_w);
    }
    // fc1
    {
        cudaFuncSetAttribute(gemm_kernel<0>,
                             cudaFuncAttributeMaxDynamicSharedMemorySize,
                             DSMEM_BYTES);
        dim3 grid(NHID / BN, BROWS / BM);
        gemm_kernel<0><<<grid, GTHR, DSMEM_BYTES>>>(
            h0h, h0l, w1h, w1l, fc1_b, K1PAD, h1h, h1l, nullptr);
    }
    // fc2
    {
        cudaFuncSetAttribute(gemm_kernel<1>,
                             cudaFuncAttributeMaxDynamicSharedMemorySize,
                             DSMEM_BYTES);
        dim3 grid(NHID / BN, BROWS / BM);
        gemm_kernel<1><<<grid, GTHR, DSMEM_BYTES>>>(
            h1h, h1l, w2h, w2l, fc2_b, K2, nullptr, nullptr, h2);
    }
    // out layer
    out_kernel<<<BROWS / 4, 128>>>(h2, out_w, out_b, out);
}

// round 11
// speedup vs baseline: 6.9478x; 1.0286x over previous
#include <cuda_runtime.h>
#include <cuda_bf16.h>
#include <cstdint>

// ---------------------------------------------------------------------------
// DigitConvolutionalModel via warp-level mma.sync (bf16 split hi/lo, fp32
// accum). R11: B-fragment software pipelining; out-layer fused into gemm<1>
// epilogue (atomicAdd partials, out pre-init to bias); packed conv writes.
//   conv_split: conv3x3 -> h0 hi/lo bf16 [B][704]
//   wprep:      split fc1_w (pad 676->704) and fc2_w into hi/lo bf16
//   out_init:   out[b][o] = out_b[o]
//   gemm<0>:    h1 = relu(h0 @ w1^T + b1) -> split bf16 h1 hi/lo
//   gemm<1>:    h2 = relu(h1 @ w2^T + b2); out += h2-slice @ out_w^T (fused)
// 3 MMA passes per k-step: Ah*Bh + Ah*Bl + Al*Bh (Al*Bl ~2^-16, dropped).
// ---------------------------------------------------------------------------

#define BROWS  32768
#define K1RAW  676
#define K1PAD  704          // 22 * 32
#define K2     512
#define NHID   512
#define NOUT   10
#define CTHR   256

// GEMM tiling
#define BM 128
#define BN 128
#define BK 32
#define GTHR 256            // 8 warps: 4 (m) x 2 (n); warp tile 32 x 64

// dynamic smem layout (u32 units)
#define ST_A_H   0
#define ST_A_L   2560
#define ST_B_H   5120
#define ST_B_L   7680
#define ST_SIZE  10240              // one stage = 40960 B
#define ST_BIAS  (2 * ST_SIZE)      // float[128]
#define ST_OUTW  (ST_BIAS + 128)    // float[10][128]
#define DSMEM_BYTES ((2 * ST_SIZE + 128 + 1280) * 4 + 256)

// ---- scratch (static device globals; no allocation APIs) -------------------
__device__ __align__(16) __nv_bfloat16 g_h0h[(size_t)BROWS * K1PAD];
__device__ __align__(16) __nv_bfloat16 g_h0l[(size_t)BROWS * K1PAD];
__device__ __align__(16) __nv_bfloat16 g_w1h[(size_t)NHID * K1PAD];
__device__ __align__(16) __nv_bfloat16 g_w1l[(size_t)NHID * K1PAD];
__device__ __align__(16) __nv_bfloat16 g_w2h[(size_t)NHID * K2];
__device__ __align__(16) __nv_bfloat16 g_w2l[(size_t)NHID * K2];
__device__ __align__(16) __nv_bfloat16 g_h1h[(size_t)BROWS * K2];
__device__ __align__(16) __nv_bfloat16 g_h1l[(size_t)BROWS * K2];

// ---- helpers ---------------------------------------------------------------
__device__ __forceinline__ void split_bf16(float x, __nv_bfloat16& h,
                                           __nv_bfloat16& l) {
    h = __float2bfloat16(x);
    l = __float2bfloat16(x - __bfloat162float(h));
}
__device__ __forceinline__ uint32_t pack_split_hi(float a, float b,
                                                  uint32_t& lo_pack) {
    __nv_bfloat16 ha, la, hb, lb;
    split_bf16(a, ha, la);
    split_bf16(b, hb, lb);
    lo_pack = (uint32_t)__bfloat16_as_ushort(la) |
              ((uint32_t)__bfloat16_as_ushort(lb) << 16);
    return (uint32_t)__bfloat16_as_ushort(ha) |
           ((uint32_t)__bfloat16_as_ushort(hb) << 16);
}

__device__ __forceinline__ void mma16816(float* c, const uint32_t* a,
                                         const uint32_t* b) {
    asm volatile(
        "mma.sync.aligned.m16n8k16.row.col.f32.bf16.bf16.f32 "
        "{%0,%1,%2,%3}, {%4,%5,%6,%7}, {%8,%9}, {%0,%1,%2,%3};"
        : "+f"(c[0]), "+f"(c[1]), "+f"(c[2]), "+f"(c[3])
        : "r"(a[0]), "r"(a[1]), "r"(a[2]), "r"(a[3]), "r"(b[0]), "r"(b[1]));
}
#define LDSM4(r, addr) \
    asm volatile("ldmatrix.sync.aligned.m8n8.x4.shared.b16 {%0,%1,%2,%3}, [%4];" \
        : "=r"((r)[0]), "=r"((r)[1]), "=r"((r)[2]), "=r"((r)[3]) : "r"(addr))
__device__ __forceinline__ void cp16(uint32_t saddr, const void* gaddr) {
    asm volatile("cp.async.cg.shared.global [%0], [%1], 16;"
                 :: "r"(saddr), "l"(gaddr));
}
#define CP_COMMIT() asm volatile("cp.async.commit_group;" ::: "memory")
#define CP_WAIT(n)  asm volatile("cp.async.wait_group %0;" :: "n"(n) : "memory")

// ---------------------------------------------------------------------------
// conv + split, packed u32 writes (2 outputs / thread)
// ---------------------------------------------------------------------------
__global__ void conv_split_kernel(const float* __restrict__ x,
                                  const float* __restrict__ w) {
    __shared__ float sw[9];
    int tid = threadIdx.x;
    if (tid < 9) sw[tid] = w[tid];
    __syncthreads();

    size_t idx = (size_t)blockIdx.x * blockDim.x + tid;   // pair index
    if (idx >= (size_t)BROWS * (K1PAD / 2)) return;
    int b = (int)(idx / (K1PAD / 2));
    int pp = (int)(idx - (size_t)b * (K1PAD / 2));
    int p0 = pp * 2;

    float s[2] = {0.0f, 0.0f};
#pragma unroll
    for (int u = 0; u < 2; u++) {
        int p = p0 + u;
        if (p < K1RAW) {
            int i = p / 26, j = p - i * 26;
            const float* xb = x + (size_t)b * 784 + i * 28 + j;
            float acc = 0.0f;
#pragma unroll
            for (int di = 0; di < 3; di++)
#pragma unroll
                for (int dj = 0; dj < 3; dj++)
                    acc = fmaf(xb[di * 28 + dj], sw[di * 3 + dj], acc);
            s[u] = acc;
        }
    }
    uint32_t lo;
    uint32_t hi = pack_split_hi(s[0], s[1], lo);
    ((uint32_t*)g_h0h)[idx] = hi;
    ((uint32_t*)g_h0l)[idx] = lo;
}

// ---------------------------------------------------------------------------
// weight split prep
// ---------------------------------------------------------------------------
__global__ void wprep_kernel(const float* __restrict__ w1,
                             const float* __restrict__ w2) {
    int idx = blockIdx.x * blockDim.x + threadIdx.x;
    int n1 = NHID * K1PAD;
    if (idx < n1) {
        int n = idx / K1PAD, k = idx - n * K1PAD;
        float v = (k < K1RAW) ? w1[n * K1RAW + k] : 0.0f;
        __nv_bfloat16 h, l;
        split_bf16(v, h, l);
        g_w1h[idx] = h;
        g_w1l[idx] = l;
    } else {
        int j = idx - n1;
        if (j < NHID * K2) {
            float v = w2[j];
            __nv_bfloat16 h, l;
            split_bf16(v, h, l);
            g_w2h[j] = h;
            g_w2l[j] = l;
        }
    }
}

// ---------------------------------------------------------------------------
// out init: out[b][o] = out_b[o]
// ---------------------------------------------------------------------------
__global__ void out_init_kernel(const float* __restrict__ out_b,
                                float* __restrict__ out) {
    int idx = blockIdx.x * blockDim.x + threadIdx.x;
    if (idx < BROWS * NOUT) out[idx] = out_b[idx % NOUT];
}

// ---------------------------------------------------------------------------
// Tiled GEMM: C[BM x BN] = A[BM x K] @ W[BN x K]^T, split-bf16 3-pass,
// cp.async double-buffered staging, B-fragment software pipeline.
// MODE 0: out = relu(C + bias) split -> (outH, outL) bf16, width 512
// MODE 1: v = relu(C + bias); atomicAdd partial v @ out_w^T into outO
// ---------------------------------------------------------------------------
template <int MODE>
__global__ void __launch_bounds__(GTHR, 2)
gemm_kernel(const __nv_bfloat16* __restrict__ Ah,
            const __nv_bfloat16* __restrict__ Al,
            const __nv_bfloat16* __restrict__ Wh,
            const __nv_bfloat16* __restrict__ Wl,
            const float* __restrict__ bias, int K,
            __nv_bfloat16* __restrict__ outH,
            __nv_bfloat16* __restrict__ outL,
            const float* __restrict__ outW,
            float* __restrict__ outO) {
    extern __shared__ uint32_t dsm[];
    float* sBias = (float*)(dsm + ST_BIAS);
    float* sOutW = (float*)(dsm + ST_OUTW);
    const uint32_t sbase = (uint32_t)__cvta_generic_to_shared(dsm);

    const int tid = threadIdx.x;
    const int lane = tid & 31;
    const int warp = tid >> 5;
    const int wm = warp & 3;
    const int wn = warp >> 2;
    const size_t rowA0 = (size_t)blockIdx.y * BM;
    const int ncol0 = blockIdx.x * BN;

    if (tid < BN) sBias[tid] = bias[ncol0 + tid];
    if (MODE == 1) {
        for (int i = tid; i < NOUT * BN; i += GTHR) {
            int o = i >> 7, j = i & 127;
            sOutW[o * BN + j] = outW[o * NHID + ncol0 + j];
        }
    }

    float c[2][8][4];
#pragma unroll
    for (int mt = 0; mt < 2; mt++)
#pragma unroll
        for (int nt = 0; nt < 8; nt++)
#pragma unroll
            for (int i = 0; i < 4; i++) c[mt][nt][i] = 0.0f;

    const int kcn = K / BK;

    auto stage = [&](int kc, int s) {
        uint32_t sb = sbase + (uint32_t)(s * ST_SIZE * 4);
#pragma unroll
        for (int it = 0; it < 2; it++) {
            int i = tid + it * GTHR;
            int row = i >> 2, quad = i & 3;
            uint32_t soff = (uint32_t)(row * 80 + quad * 16);
            size_t ga = (rowA0 + row) * (size_t)K + kc * BK + quad * 8;
            size_t gb = (size_t)(ncol0 + row) * K + kc * BK + quad * 8;
            cp16(sb + ST_A_H * 4 + soff, Ah + ga);
            cp16(sb + ST_A_L * 4 + soff, Al + ga);
            cp16(sb + ST_B_H * 4 + soff, Wh + gb);
            cp16(sb + ST_B_L * 4 + soff, Wl + gb);
        }
    };

    stage(0, 0);
    CP_COMMIT();

    const int g = lane >> 3, lr8 = lane & 7;
    const int arsel = (g & 1) ? 8 : 0;
    const int absel = (g & 2) ? 16 : 0;
    const int brsel = (g & 2) ? 8 : 0;
    const int bbsel = (g & 1) ? 16 : 0;

    for (int kc = 0; kc < kcn; kc++) {
        if (kc + 1 < kcn) {
            stage(kc + 1, (kc + 1) & 1);
            CP_COMMIT();
            CP_WAIT(1);
        } else {
            CP_WAIT(0);
        }
        __syncthreads();

        const uint32_t sb = sbase + (uint32_t)((kc & 1) * ST_SIZE * 4);
        const uint32_t aAh = sb + ST_A_H * 4;
        const uint32_t aAl = sb + ST_A_L * 4;
        const uint32_t aBh = sb + ST_B_H * 4;
        const uint32_t aBl = sb + ST_B_L * 4;

#pragma unroll
        for (int ks = 0; ks < 2; ks++) {
            uint32_t ah[2][4], al[2][4];
#pragma unroll
            for (int mt = 0; mt < 2; mt++) {
                int r = wm * 32 + mt * 16 + lr8 + arsel;
                uint32_t off = (uint32_t)(r * 80 + ks * 32 + absel);
                LDSM4(ah[mt], aAh + off);
                LDSM4(al[mt], aAl + off);
            }
            // B fragment pipeline: double-buffered over np
            uint32_t bhq[2][4], blq[2][4];
            {
                int nr = wn * 64 + lr8 + brsel;
                uint32_t off = (uint32_t)(nr * 80 + ks * 32 + bbsel);
                LDSM4(bhq[0], aBh + off);
                LDSM4(blq[0], aBl + off);
            }
#pragma unroll
            for (int np = 0; np < 4; np++) {
                const int cur = np & 1;
                if (np < 3) {
                    int nr = wn * 64 + (np + 1) * 16 + lr8 + brsel;
                    uint32_t off = (uint32_t)(nr * 80 + ks * 32 + bbsel);
                    LDSM4(bhq[cur ^ 1], aBh + off);
                    LDSM4(blq[cur ^ 1], aBl + off);
                }
#pragma unroll
                for (int hf = 0; hf < 2; hf++) {
                    int nt = np * 2 + hf;
#pragma unroll
                    for (int mt = 0; mt < 2; mt++) {
                        mma16816(c[mt][nt], ah[mt], bhq[cur] + 2 * hf);
                        mma16816(c[mt][nt], ah[mt], blq[cur] + 2 * hf);
                        mma16816(c[mt][nt], al[mt], bhq[cur] + 2 * hf);
                    }
                }
            }
        }
        __syncthreads();
    }

    // epilogue (c-frag: c0,c1 -> row lq, cols 2lr,2lr+1; c2,c3 -> row lq+8)
    const int lq = lane >> 2;
    const int lr = lane & 3;
#pragma unroll
    for (int mt = 0; mt < 2; mt++) {
        size_t r0 = rowA0 + wm * 32 + mt * 16 + lq;
        size_t r1 = r0 + 8;
        float p0[NOUT], p1[NOUT];
        if (MODE == 1) {
#pragma unroll
            for (int o = 0; o < NOUT; o++) { p0[o] = 0.0f; p1[o] = 0.0f; }
        }
#pragma unroll
        for (int nt = 0; nt < 8; nt++) {
            int nl = wn * 64 + nt * 8 + lr * 2;
            int ng = ncol0 + nl;
            float b0 = sBias[nl], b1 = sBias[nl + 1];
            float v00 = fmaxf(c[mt][nt][0] + b0, 0.0f);
            float v01 = fmaxf(c[mt][nt][1] + b1, 0.0f);
            float v10 = fmaxf(c[mt][nt][2] + b0, 0.0f);
            float v11 = fmaxf(c[mt][nt][3] + b1, 0.0f);
            if (MODE == 0) {
                uint32_t lo0, lo1;
                uint32_t hi0 = pack_split_hi(v00, v01, lo0);
                uint32_t hi1 = pack_split_hi(v10, v11, lo1);
                *(uint32_t*)(outH + r0 * NHID + ng) = hi0;
                *(uint32_t*)(outL + r0 * NHID + ng) = lo0;
                *(uint32_t*)(outH + r1 * NHID + ng) = hi1;
                *(uint32_t*)(outL + r1 * NHID + ng) = lo1;
            } else {
#pragma unroll
                for (int o = 0; o < NOUT; o++) {
                    float w0 = sOutW[o * BN + nl];
                    float w1 = sOutW[o * BN + nl + 1];
                    p0[o] = fmaf(v00, w0, fmaf(v01, w1, p0[o]));
                    p1[o] = fmaf(v10, w0, fmaf(v11, w1, p1[o]));
                }
            }
        }
        if (MODE == 1) {
#pragma unroll
            for (int off = 1; off <= 2; off <<= 1)
#pragma unroll
                for (int o = 0; o < NOUT; o++) {
                    p0[o] += __shfl_xor_sync(0xFFFFFFFF, p0[o], off);
                    p1[o] += __shfl_xor_sync(0xFFFFFFFF, p1[o], off);
                }
            if (lr == 0) {
#pragma unroll
                for (int o = 0; o < NOUT; o++) {
                    atomicAdd(outO + r0 * NOUT + o, p0[o]);
                    atomicAdd(outO + r1 * NOUT + o, p1[o]);
                }
            }
        }
    }
}

// ---------------------------------------------------------------------------
// Launch
// ---------------------------------------------------------------------------
extern "C" void kernel_launch(void* const* d_in, const int* in_sizes, int n_in,
                              void* d_out, int out_size) {
    const float* x      = (const float*)d_in[0];
    const float* conv_w = (const float*)d_in[1];
    const float* fc1_w  = (const float*)d_in[2];
    const float* fc1_b  = (const float*)d_in[3];
    const float* fc2_w  = (const float*)d_in[4];
    const float* fc2_b  = (const float*)d_in[5];
    const float* out_w  = (const float*)d_in[6];
    const float* out_b  = (const float*)d_in[7];
    float* out = (float*)d_out;

    __nv_bfloat16 *h0h, *h0l, *w1h, *w1l, *w2h, *w2l, *h1h, *h1l;
    cudaGetSymbolAddress((void**)&h0h, g_h0h);
    cudaGetSymbolAddress((void**)&h0l, g_h0l);
    cudaGetSymbolAddress((void**)&w1h, g_w1h);
    cudaGetSymbolAddress((void**)&w1l, g_w1l);
    cudaGetSymbolAddress((void**)&w2h, g_w2h);
    cudaGetSymbolAddress((void**)&w2l, g_w2l);
    cudaGetSymbolAddress((void**)&h1h, g_h1h);
    cudaGetSymbolAddress((void**)&h1l, g_h1l);

    // weight split
    {
        int total = NHID * K1PAD + NHID * K2;
        wprep_kernel<<<(total + CTHR - 1) / CTHR, CTHR>>>(fc1_w, fc2_w);
    }
    // conv + split (pair-packed)
    {
        size_t total = (size_t)BROWS * (K1PAD / 2);
        conv_split_kernel<<<(int)((total + CTHR - 1) / CTHR), CTHR>>>(x, conv_w);
    }
    // out init (bias)
    out_init_kernel<<<(BROWS * NOUT + CTHR - 1) / CTHR, CTHR>>>(out_b, out);
    // fc1
    {
        cudaFuncSetAttribute(gemm_kernel<0>,
                             cudaFuncAttributeMaxDynamicSharedMemorySize,
                             DSMEM_BYTES);
        dim3 grid(NHID / BN, BROWS / BM);
        gemm_kernel<0><<<grid, GTHR, DSMEM_BYTES>>>(
            h0h, h0l, w1h, w1l, fc1_b, K1PAD, h1h, h1l, nullptr, nullptr);
    }
    // fc2 + fused out-layer
    {
        cudaFuncSetAttribute(gemm_kernel<1>,
                             cudaFuncAttributeMaxDynamicSharedMemorySize,
                             DSMEM_BYTES);
        dim3 grid(NHID / BN, BROWS / BM);
        gemm_kernel<1><<<grid, GTHR, DSMEM_BYTES>>>(
            h1h, h1l, w2h, w2l, fc2_b, K2, nullptr, nullptr, out_w, out);
    }
}